// round 15
// baseline (speedup 1.0000x reference)
#include <cuda_runtime.h>
#include <cuda_bf16.h>
#include <cstdint>
#include <cstddef>

#define NT 4096   // sequence length
#define DD 1024   // head dim

// ---------------- device scratch (no allocs allowed) ----------------
// g_S0: qk logits (full, unsplit); later parts 0-3 of pv split-K partials.
// g_S1: parts 4-7 of pv split-K partials.
__device__ float         g_S0[(size_t)NT * NT];    // 64 MB
__device__ float         g_S1[(size_t)NT * NT];    // 64 MB
__device__ __nv_bfloat16 g_Qh[(size_t)NT * DD];
__device__ __nv_bfloat16 g_Ql[(size_t)NT * DD];
__device__ __nv_bfloat16 g_Kh[(size_t)NT * DD];
__device__ __nv_bfloat16 g_Kl[(size_t)NT * DD];
__device__ __nv_bfloat16 g_Ph[(size_t)NT * NT];    // 32 MB
__device__ __nv_bfloat16 g_Pl[(size_t)NT * NT];    // 32 MB
__device__ __nv_bfloat16 g_Vth[(size_t)DD * NT];   // V^T hi  [1024][4096]
__device__ __nv_bfloat16 g_Vtl[(size_t)DD * NT];   // V^T lo

// ---------------- helpers ----------------
__device__ __forceinline__ uint32_t smem_u32(const void* p) {
    uint32_t a;
    asm("{ .reg .u64 t; cvta.to.shared.u64 t, %1; cvt.u32.u64 %0, t; }" : "=r"(a) : "l"(p));
    return a;
}
// SW64 swizzle for 64-byte rows: XOR 16B-column bits [5:4] with row bits [8:7]
#define SWZ64(b) ((b) ^ (((b) >> 3) & 0x30))

__device__ __forceinline__ void cp_async16(uint32_t dst, const void* src) {
    asm volatile("cp.async.cg.shared.global [%0], [%1], 16;" :: "r"(dst), "l"(src));
}
__device__ __forceinline__ void cp_commit() { asm volatile("cp.async.commit_group;" ::: "memory"); }
template<int N> __device__ __forceinline__ void cp_wait() {
    asm volatile("cp.async.wait_group %0;" :: "n"(N) : "memory");
}

__device__ __forceinline__ void ldsm_x4(uint32_t& r0, uint32_t& r1, uint32_t& r2, uint32_t& r3,
                                        uint32_t addr) {
    asm volatile("ldmatrix.sync.aligned.m8n8.x4.shared.b16 {%0,%1,%2,%3}, [%4];"
                 : "=r"(r0), "=r"(r1), "=r"(r2), "=r"(r3) : "r"(addr));
}

__device__ __forceinline__ void mma16816(float* d, const uint32_t* a, uint32_t b0, uint32_t b1) {
    asm volatile(
        "mma.sync.aligned.m16n8k16.row.col.f32.bf16.bf16.f32 "
        "{%0,%1,%2,%3}, {%4,%5,%6,%7}, {%8,%9}, {%0,%1,%2,%3};"
        : "+f"(d[0]), "+f"(d[1]), "+f"(d[2]), "+f"(d[3])
        : "r"(a[0]), "r"(a[1]), "r"(a[2]), "r"(a[3]), "r"(b0), "r"(b1));
}

__device__ __forceinline__ uint32_t packbf(__nv_bfloat16 a, __nv_bfloat16 b) {
    __nv_bfloat162 t; t.x = a; t.y = b;
    return *reinterpret_cast<uint32_t*>(&t);
}

// ---------------- GEMM config: fused-phase engine ----------------
// Tile 128(M) x 128(N) x 32(K). Each stage holds ALL FOUR operand tiles
// (Ah, Al, Bh, Bl) so hh+lh+hl accumulate in one pass over K: 4 tile-streams
// instead of 6, 4.0 MMAs per LDSM instead of 2.67, 96 MMAs per barrier pair.
constexpr int GBM = 128, GBN = 128, GBK = 32;
constexpr int TILE_B = GBM * 64;                 // 8 KB per operand tile (128 rows x 64B)
constexpr int STAGE_BYTES = 4 * TILE_B;          // 32 KB per stage
constexpr int SMEM_NEED = 2 * STAGE_BYTES;       // 64 KB -> 2 CTAs/SM
constexpr int SMEM_TOTAL = SMEM_NEED + 1024;

// D = (Ah+Al)*(Bh+Bl)^T dropping Al*Bl, accumulated per-k-step into one acc.
// A: K-major stride LDA; B: K-major stride LDB; C row-major stride LDC.
// Part z: A/B advance z*KEXT along K; C = (z<PPB ? C0 : C1) + (z%PPB)*PART_STR.
template<int LDA, int LDB, int LDC, long long PART_STR, int KEXT, int PPB>
__global__ void __launch_bounds__(256, 2)
mma_gemm(const __nv_bfloat16* __restrict__ Ah, const __nv_bfloat16* __restrict__ Al,
         const __nv_bfloat16* __restrict__ Bh, const __nv_bfloat16* __restrict__ Bl,
         float* __restrict__ C0, float* __restrict__ C1)
{
    extern __shared__ char smem_raw[];
    const uint32_t sb = (smem_u32(smem_raw) + 1023u) & ~1023u;
    const int tid = threadIdx.x;
    const int wid = tid >> 5;
    const int lane = tid & 31;
    const int m0 = blockIdx.y * GBM;
    const int n0 = blockIdx.x * GBN;

    const int z = blockIdx.z;
    const size_t kbase = (size_t)z * KEXT;
    Ah += kbase; Al += kbase; Bh += kbase; Bl += kbase;
    float* __restrict__ C = (z < PPB) ? C0 : C1;
    C += (size_t)(z % PPB) * (size_t)PART_STR;

    const int wm = wid & 3;        // 4 warp-rows of 32
    const int wn = wid >> 2;       // 2 warp-cols of 64

    constexpr int NCHUNKS = KEXT / GBK;   // single pass over K (phases fused)

    auto load_chunk = [&](int c, int s) {
        const int koff = c * GBK;
        const char* srcs[4] = {
            (const char*)(Ah + (size_t)m0 * LDA + koff),
            (const char*)(Al + (size_t)m0 * LDA + koff),
            (const char*)(Bh + (size_t)n0 * LDB + koff),
            (const char*)(Bl + (size_t)n0 * LDB + koff)
        };
        const int rowstride[4] = {LDA * 2, LDA * 2, LDB * 2, LDB * 2};
        const uint32_t stage = sb + s * STAGE_BYTES;
        #pragma unroll
        for (int tile = 0; tile < 4; tile++) {
            const uint32_t base = stage + tile * TILE_B;
            #pragma unroll
            for (int t = 0; t < 2; t++) {
                int idx = tid + t * 256;
                int r  = idx >> 2;           // row 0..127
                int cB = (idx & 3) * 16;     // 16B unit within 64B row
                cp_async16(base + SWZ64(r * 64 + cB),
                           srcs[tile] + (size_t)r * rowstride[tile] + cB);
            }
        }
    };

    float acc[2][8][4];
    #pragma unroll
    for (int i = 0; i < 2; i++)
        #pragma unroll
        for (int j = 0; j < 8; j++)
            #pragma unroll
            for (int q = 0; q < 4; q++) acc[i][j][q] = 0.0f;

    load_chunk(0, 0); cp_commit();
    load_chunk(1, 1); cp_commit();

    // per-lane ldmatrix address components (64B rows)
    const int a_row  = wm * 32 + (lane & 15);
    const int a_csel = (lane >> 4) << 4;                     // 0 / 16 bytes
    const int b_row  = wn * 64 + (lane & 7) + ((lane >> 4) << 3);
    const int b_csel = ((lane >> 3) & 1) << 4;               // 0 / 16 bytes

    for (int c = 0; c < NCHUNKS; c++) {
        const int s = c & 1;
        cp_wait<1>();
        __syncthreads();
        const uint32_t aHi = sb + s * STAGE_BYTES;
        const uint32_t aLo = aHi + TILE_B;
        const uint32_t bHi = aHi + 2 * TILE_B;
        const uint32_t bLo = aHi + 3 * TILE_B;
        #pragma unroll
        for (int ksl = 0; ksl < 2; ksl++) {      // two K=16 steps per 32-K chunk
            const int ko = ksl * 32;             // byte offset within 64B row
            uint32_t ah[2][4], al[2][4], bf[4][4];
            #pragma unroll
            for (int mi = 0; mi < 2; mi++) {
                const uint32_t off = (a_row + mi * 16) * 64 + ko + a_csel;
                ldsm_x4(ah[mi][0], ah[mi][1], ah[mi][2], ah[mi][3], aHi + SWZ64(off));
                ldsm_x4(al[mi][0], al[mi][1], al[mi][2], al[mi][3], aLo + SWZ64(off));
            }
            #pragma unroll
            for (int ni = 0; ni < 4; ni++) {
                const uint32_t off = (b_row + ni * 16) * 64 + ko + b_csel;
                ldsm_x4(bf[ni][0], bf[ni][1], bf[ni][2], bf[ni][3], bHi + SWZ64(off));
            }
            // hh + lh on Bh fragments
            #pragma unroll
            for (int ni = 0; ni < 4; ni++) {
                #pragma unroll
                for (int mi = 0; mi < 2; mi++) {
                    mma16816(acc[mi][ni * 2 + 0], ah[mi], bf[ni][0], bf[ni][1]);
                    mma16816(acc[mi][ni * 2 + 1], ah[mi], bf[ni][2], bf[ni][3]);
                }
                #pragma unroll
                for (int mi = 0; mi < 2; mi++) {
                    mma16816(acc[mi][ni * 2 + 0], al[mi], bf[ni][0], bf[ni][1]);
                    mma16816(acc[mi][ni * 2 + 1], al[mi], bf[ni][2], bf[ni][3]);
                }
            }
            // reload B fragments as Bl, then hl
            #pragma unroll
            for (int ni = 0; ni < 4; ni++) {
                const uint32_t off = (b_row + ni * 16) * 64 + ko + b_csel;
                ldsm_x4(bf[ni][0], bf[ni][1], bf[ni][2], bf[ni][3], bLo + SWZ64(off));
            }
            #pragma unroll
            for (int ni = 0; ni < 4; ni++) {
                #pragma unroll
                for (int mi = 0; mi < 2; mi++) {
                    mma16816(acc[mi][ni * 2 + 0], ah[mi], bf[ni][0], bf[ni][1]);
                    mma16816(acc[mi][ni * 2 + 1], ah[mi], bf[ni][2], bf[ni][3]);
                }
            }
        }
        __syncthreads();
        if (c + 2 < NCHUNKS) { load_chunk(c + 2, s); }
        cp_commit();
    }

    // ---- epilogue ----
    const int er = lane >> 2;            // 0..7
    const int ec = (lane & 3) * 2;       // 0,2,4,6
    #pragma unroll
    for (int mi = 0; mi < 2; mi++) {
        #pragma unroll
        for (int j = 0; j < 8; j++) {
            float* base = C + (size_t)(m0 + wm * 32 + mi * 16 + er) * LDC
                            + n0 + wn * 64 + j * 8 + ec;
            *reinterpret_cast<float2*>(base) = make_float2(acc[mi][j][0], acc[mi][j][1]);
            *reinterpret_cast<float2*>(base + (size_t)8 * LDC) = make_float2(acc[mi][j][2], acc[mi][j][3]);
        }
    }
}

// ---------------- split-K reduction: out = sum of 8 partials (4 in S0, 4 in S1) ----------------
__global__ void __launch_bounds__(256) reduce8_kernel(float* __restrict__ out)
{
    const size_t i = (size_t)blockIdx.x * blockDim.x + threadIdx.x;   // float4 index
    const float4* p0 = reinterpret_cast<const float4*>(g_S0);
    const float4* p1 = reinterpret_cast<const float4*>(g_S1);
    constexpr size_t PART4 = (size_t)NT * DD / 4;
    float s0 = 0.f, s1 = 0.f, s2 = 0.f, s3 = 0.f;
    #pragma unroll
    for (int p = 0; p < 4; p++) {
        float4 a = p0[i + p * PART4];
        float4 b = p1[i + p * PART4];
        s0 += a.x + b.x; s1 += a.y + b.y; s2 += a.z + b.z; s3 += a.w + b.w;
    }
    reinterpret_cast<float4*>(out)[i] = make_float4(s0, s1, s2, s3);
}

// ---------------- fp32 -> bf16 hi/lo split ----------------
__global__ void __launch_bounds__(256) split_kernel(const float* __restrict__ x,
                                                    __nv_bfloat16* __restrict__ hi,
                                                    __nv_bfloat16* __restrict__ lo,
                                                    int n4)
{
    int i = blockIdx.x * blockDim.x + threadIdx.x;
    if (i >= n4) return;
    float4 v = reinterpret_cast<const float4*>(x)[i];
    __nv_bfloat16 h0 = __float2bfloat16(v.x), h1 = __float2bfloat16(v.y);
    __nv_bfloat16 h2 = __float2bfloat16(v.z), h3 = __float2bfloat16(v.w);
    __nv_bfloat16 l0 = __float2bfloat16(v.x - __bfloat162float(h0));
    __nv_bfloat16 l1 = __float2bfloat16(v.y - __bfloat162float(h1));
    __nv_bfloat16 l2 = __float2bfloat16(v.z - __bfloat162float(h2));
    __nv_bfloat16 l3 = __float2bfloat16(v.w - __bfloat162float(h3));
    reinterpret_cast<uint2*>(hi)[i] = make_uint2(packbf(h0, h1), packbf(h2, h3));
    reinterpret_cast<uint2*>(lo)[i] = make_uint2(packbf(l0, l1), packbf(l2, l3));
}

// ---------------- V transpose + split:  Vt[n][k] = V[k][n] ----------------
__global__ void __launch_bounds__(256) vtrans_kernel(const float* __restrict__ v)
{
    __shared__ float tile[32][33];
    const int n0 = blockIdx.x * 32;   // over DD
    const int k0 = blockIdx.y * 32;   // over NT
    const int tx = threadIdx.x, ty = threadIdx.y;  // (32, 8)
    #pragma unroll
    for (int j = 0; j < 32; j += 8)
        tile[ty + j][tx] = v[(size_t)(k0 + ty + j) * DD + n0 + tx];
    __syncthreads();
    #pragma unroll
    for (int j = 0; j < 32; j += 8) {
        const float val = tile[tx][ty + j];
        __nv_bfloat16 h = __float2bfloat16(val);
        __nv_bfloat16 l = __float2bfloat16(val - __bfloat162float(h));
        const size_t o = (size_t)(n0 + ty + j) * NT + k0 + tx;
        g_Vth[o] = h;
        g_Vtl[o] = l;
    }
}

// ---------------- softmax over S0 + normalize + bf16 hi/lo split of P ----------------
__global__ void __launch_bounds__(256) softmax_split()
{
    const int row = blockIdx.x;
    const int tid = threadIdx.x;
    const float4* p4 = reinterpret_cast<const float4*>(g_S0 + (size_t)row * NT);
    __shared__ float red[8];
    __shared__ float sh_inv;

    float4 v[4];
    #pragma unroll
    for (int it = 0; it < 4; it++) v[it] = p4[tid + it * 256];

    float m = -3.4e38f;
    #pragma unroll
    for (int it = 0; it < 4; it++)
        m = fmaxf(m, fmaxf(fmaxf(v[it].x, v[it].y), fmaxf(v[it].z, v[it].w)));
    #pragma unroll
    for (int o = 16; o > 0; o >>= 1) m = fmaxf(m, __shfl_xor_sync(0xffffffffu, m, o));
    if ((tid & 31) == 0) red[tid >> 5] = m;
    __syncthreads();
    float M = red[0];
    #pragma unroll
    for (int i = 1; i < 8; i++) M = fmaxf(M, red[i]);
    __syncthreads();

    float s = 0.0f;
    #pragma unroll
    for (int it = 0; it < 4; it++) {
        v[it].x = __expf(v[it].x - M);
        v[it].y = __expf(v[it].y - M);
        v[it].z = __expf(v[it].z - M);
        v[it].w = __expf(v[it].w - M);
        s += (v[it].x + v[it].y) + (v[it].z + v[it].w);
    }
    #pragma unroll
    for (int o = 16; o > 0; o >>= 1) s += __shfl_xor_sync(0xffffffffu, s, o);
    if ((tid & 31) == 0) red[tid >> 5] = s;
    __syncthreads();
    if (tid == 0) {
        float tot = 0.0f;
        #pragma unroll
        for (int i = 0; i < 8; i++) tot += red[i];
        sh_inv = 1.0f / tot;
    }
    __syncthreads();
    const float inv = sh_inv;

    uint2* ph2 = reinterpret_cast<uint2*>(g_Ph + (size_t)row * NT);
    uint2* pl2 = reinterpret_cast<uint2*>(g_Pl + (size_t)row * NT);
    #pragma unroll
    for (int it = 0; it < 4; it++) {
        float p0v = v[it].x * inv, p1v = v[it].y * inv, p2v = v[it].z * inv, p3v = v[it].w * inv;
        __nv_bfloat16 h0 = __float2bfloat16(p0v), h1 = __float2bfloat16(p1v);
        __nv_bfloat16 h2 = __float2bfloat16(p2v), h3 = __float2bfloat16(p3v);
        __nv_bfloat16 l0 = __float2bfloat16(p0v - __bfloat162float(h0));
        __nv_bfloat16 l1 = __float2bfloat16(p1v - __bfloat162float(h1));
        __nv_bfloat16 l2 = __float2bfloat16(p2v - __bfloat162float(h2));
        __nv_bfloat16 l3 = __float2bfloat16(p3v - __bfloat162float(h3));
        const int idx = tid + it * 256;
        ph2[idx] = make_uint2(packbf(h0, h1), packbf(h2, h3));
        pl2[idx] = make_uint2(packbf(l0, l1), packbf(l2, l3));
    }
}

// ---------------- launch ----------------
extern "C" void kernel_launch(void* const* d_in, const int* in_sizes, int n_in,
                              void* d_out, int out_size)
{
    const float* q = (const float*)d_in[0];
    const float* k = (const float*)d_in[1];
    const float* v = (const float*)d_in[2];
    float* out = (float*)d_out;

    void *qh, *ql, *kh, *kl, *s0, *s1, *ph, *pl, *vth, *vtl;
    cudaGetSymbolAddress(&qh, g_Qh);  cudaGetSymbolAddress(&ql, g_Ql);
    cudaGetSymbolAddress(&kh, g_Kh);  cudaGetSymbolAddress(&kl, g_Kl);
    cudaGetSymbolAddress(&s0, g_S0);  cudaGetSymbolAddress(&s1, g_S1);
    cudaGetSymbolAddress(&ph, g_Ph);  cudaGetSymbolAddress(&pl, g_Pl);
    cudaGetSymbolAddress(&vth, g_Vth); cudaGetSymbolAddress(&vtl, g_Vtl);

    // qk: unsplit, fused-phase: A=Q, B=K, KEXT=1024 -> full S in g_S0
    auto qk = mma_gemm<DD, DD, NT, 0LL, 1024, 1>;
    // pv: split-K x8, fused-phase: KEXT=512, 4 parts in S0 + 4 in S1
    auto pv = mma_gemm<NT, NT, DD, (long long)NT * DD, 512, 4>;
    cudaFuncSetAttribute(qk, cudaFuncAttributeMaxDynamicSharedMemorySize, SMEM_TOTAL);
    cudaFuncSetAttribute(pv, cudaFuncAttributeMaxDynamicSharedMemorySize, SMEM_TOTAL);

    const int n4 = NT * DD / 4;
    split_kernel<<<(n4 + 255) / 256, 256>>>(q, (__nv_bfloat16*)qh, (__nv_bfloat16*)ql, n4);
    split_kernel<<<(n4 + 255) / 256, 256>>>(k, (__nv_bfloat16*)kh, (__nv_bfloat16*)kl, n4);
    vtrans_kernel<<<dim3(DD / 32, NT / 32), dim3(32, 8)>>>(v);

    // S = Q K^T   (grid 32 x 32 = 1024 CTAs)
    qk<<<dim3(NT / GBN, NT / GBM, 1), 256, SMEM_TOTAL>>>(
        (const __nv_bfloat16*)qh, (const __nv_bfloat16*)ql,
        (const __nv_bfloat16*)kh, (const __nv_bfloat16*)kl,
        (float*)s0, (float*)s1);

    softmax_split<<<NT, 256>>>();

    // O = P V via split-K x8  (grid 8 x 32 x 8 = 2048 CTAs)
    pv<<<dim3(DD / GBN, NT / GBM, 8), 256, SMEM_TOTAL>>>(
        (const __nv_bfloat16*)ph, (const __nv_bfloat16*)pl,
        (const __nv_bfloat16*)vth, (const __nv_bfloat16*)vtl,
        (float*)s0, (float*)s1);

    reduce8_kernel<<<(NT * DD / 4) / 256, 256>>>(out);
}

// round 16
// speedup vs baseline: 1.0359x; 1.0359x over previous
#include <cuda_runtime.h>
#include <cuda_bf16.h>
#include <cstdint>
#include <cstddef>

#define NT 4096   // sequence length
#define DD 1024   // head dim

// ---------------- device scratch (no allocs allowed) ----------------
// g_S0: qk logits (full, unsplit); later parts 0-3 of pv split-K partials.
// g_S1: parts 4-7 of pv split-K partials.
__device__ float         g_S0[(size_t)NT * NT];    // 64 MB
__device__ float         g_S1[(size_t)NT * NT];    // 64 MB
__device__ __nv_bfloat16 g_Qh[(size_t)NT * DD];
__device__ __nv_bfloat16 g_Ql[(size_t)NT * DD];
__device__ __nv_bfloat16 g_Kh[(size_t)NT * DD];
__device__ __nv_bfloat16 g_Kl[(size_t)NT * DD];
__device__ __nv_bfloat16 g_Ph[(size_t)NT * NT];    // 32 MB
__device__ __nv_bfloat16 g_Pl[(size_t)NT * NT];    // 32 MB
__device__ __nv_bfloat16 g_Vth[(size_t)DD * NT];   // V^T hi  [1024][4096]
__device__ __nv_bfloat16 g_Vtl[(size_t)DD * NT];   // V^T lo

// ---------------- helpers ----------------
__device__ __forceinline__ uint32_t smem_u32(const void* p) {
    uint32_t a;
    asm("{ .reg .u64 t; cvta.to.shared.u64 t, %1; cvt.u32.u64 %0, t; }" : "=r"(a) : "l"(p));
    return a;
}
#define SMEM_SWZ128(b) ((b) ^ (((b) >> 3) & 0x70))

__device__ __forceinline__ void cp_async16(uint32_t dst, const void* src) {
    asm volatile("cp.async.cg.shared.global [%0], [%1], 16;" :: "r"(dst), "l"(src));
}
__device__ __forceinline__ void cp_commit() { asm volatile("cp.async.commit_group;" ::: "memory"); }
template<int N> __device__ __forceinline__ void cp_wait() {
    asm volatile("cp.async.wait_group %0;" :: "n"(N) : "memory");
}

__device__ __forceinline__ void ldsm_x4(uint32_t& r0, uint32_t& r1, uint32_t& r2, uint32_t& r3,
                                        uint32_t addr) {
    asm volatile("ldmatrix.sync.aligned.m8n8.x4.shared.b16 {%0,%1,%2,%3}, [%4];"
                 : "=r"(r0), "=r"(r1), "=r"(r2), "=r"(r3) : "r"(addr));
}

__device__ __forceinline__ void mma16816(float* d, const uint32_t* a, uint32_t b0, uint32_t b1) {
    asm volatile(
        "mma.sync.aligned.m16n8k16.row.col.f32.bf16.bf16.f32 "
        "{%0,%1,%2,%3}, {%4,%5,%6,%7}, {%8,%9}, {%0,%1,%2,%3};"
        : "+f"(d[0]), "+f"(d[1]), "+f"(d[2]), "+f"(d[3])
        : "r"(a[0]), "r"(a[1]), "r"(a[2]), "r"(a[3]), "r"(b0), "r"(b1));
}

__device__ __forceinline__ uint32_t packbf(__nv_bfloat16 a, __nv_bfloat16 b) {
    __nv_bfloat162 t; t.x = a; t.y = b;
    return *reinterpret_cast<uint32_t*>(&t);
}

// ---------------- GEMM config ----------------
// R4 core tile (128x128x64, proven best in-wave engine), but with a 3-stage
// ring and ONE __syncthreads per chunk. The prefetch load is issued AFTER the
// MMA block (overwrites the stage consumed in chunk c-1, which the top-of-chunk
// barrier proves is drained) so the cp.async issue burst overlaps other warps'
// MMA tails instead of sitting in the post-barrier critical path (R5's mistake).
constexpr int GBM = 128, GBN = 128, GBK = 64;   // K chunk = 64 bf16 = 128B row
constexpr int NSTG = 3;
constexpr int TILE_BYTES = GBM * 128;            // 16 KB (A or B tile per stage)
constexpr int STAGE_BYTES = 2 * TILE_BYTES;      // 32 KB per stage (A+B)
constexpr int SMEM_NEED = NSTG * STAGE_BYTES;    // 96 KB -> still 2 CTAs/SM
constexpr int SMEM_TOTAL = SMEM_NEED + 1024;

// D[m][n] = Ah*Bh + Al*Bh + Ah*Bl over K = KEXT (split-K part blockIdx.z).
// A: K-major stride LDA; B: K-major stride LDB; C row-major stride LDC.
// Part z: A/B advance z*KEXT along K; C = (z<PPB ? C0 : C1) + (z%PPB)*PART_STR.
template<int LDA, int LDB, int LDC, long long PART_STR, int KEXT, int PPB>
__global__ void __launch_bounds__(256, 2)
mma_gemm(const __nv_bfloat16* __restrict__ Ah, const __nv_bfloat16* __restrict__ Al,
         const __nv_bfloat16* __restrict__ Bh, const __nv_bfloat16* __restrict__ Bl,
         float* __restrict__ C0, float* __restrict__ C1)
{
    extern __shared__ char smem_raw[];
    const uint32_t sb = (smem_u32(smem_raw) + 1023u) & ~1023u;
    const int tid = threadIdx.x;
    const int wid = tid >> 5;
    const int lane = tid & 31;
    const int m0 = blockIdx.y * GBM;
    const int n0 = blockIdx.x * GBN;

    const int z = blockIdx.z;
    const size_t kbase = (size_t)z * KEXT;
    Ah += kbase; Al += kbase; Bh += kbase; Bl += kbase;
    float* __restrict__ C = (z < PPB) ? C0 : C1;
    C += (size_t)(z % PPB) * (size_t)PART_STR;

    const int wm = wid & 3;        // 4 warp-rows of 32
    const int wn = wid >> 2;       // 2 warp-cols of 64

    constexpr int CPP = KEXT / GBK;       // chunks per phase
    constexpr int NCHUNKS = 3 * CPP;      // hh, lh, hl

    const __nv_bfloat16* Asrc[3] = {Ah, Al, Ah};
    const __nv_bfloat16* Bsrc[3] = {Bh, Bh, Bl};

    auto load_chunk = [&](int c, int s) {
        const int ph = c / CPP;
        const int koff = (c % CPP) * GBK;
        const char* srcA = (const char*)(Asrc[ph] + (size_t)m0 * LDA + koff);
        const char* srcB = (const char*)(Bsrc[ph] + (size_t)n0 * LDB + koff);
        const uint32_t baseA = sb + s * STAGE_BYTES;
        const uint32_t baseB = baseA + TILE_BYTES;
        #pragma unroll
        for (int t = 0; t < 4; t++) {
            int idx = tid + t * 256;
            int r = idx >> 3;
            int cB = (idx & 7) * 16;
            cp_async16(baseA + SMEM_SWZ128(r * 128 + cB), srcA + (size_t)r * (LDA * 2) + cB);
        }
        #pragma unroll
        for (int t = 0; t < 4; t++) {
            int idx = tid + t * 256;
            int r = idx >> 3;
            int cB = (idx & 7) * 16;
            cp_async16(baseB + SMEM_SWZ128(r * 128 + cB), srcB + (size_t)r * (LDB * 2) + cB);
        }
        cp_commit();
    };

    float acc[2][8][4];
    #pragma unroll
    for (int i = 0; i < 2; i++)
        #pragma unroll
        for (int j = 0; j < 8; j++)
            #pragma unroll
            for (int q = 0; q < 4; q++) acc[i][j][q] = 0.0f;

    // prologue: 2 chunks in flight
    load_chunk(0, 0);
    load_chunk(1, 1);

    // per-lane ldmatrix address components
    const int a_row  = wm * 32 + (lane & 15);
    const int a_csel = (lane >> 4) << 4;                     // 0 / 16 bytes
    const int b_row  = wn * 64 + (lane & 7) + ((lane >> 4) << 3);
    const int b_csel = ((lane >> 3) & 1) << 4;               // 0 / 16 bytes

    for (int c = 0; c < NCHUNKS; c++) {
        const int s = c % NSTG;
        cp_wait<1>();             // group(c) arrived (groups complete in order)
        __syncthreads();          // every warp finished chunk c-1 -> stage (c+2)%3 free
        const uint32_t aBase = sb + s * STAGE_BYTES;
        const uint32_t bBase = aBase + TILE_BYTES;
        #pragma unroll
        for (int ks = 0; ks < 4; ks++) {
            uint32_t afr[2][4];
            #pragma unroll
            for (int mi = 0; mi < 2; mi++) {
                uint32_t addr = aBase + SMEM_SWZ128((a_row + mi * 16) * 128 + ks * 32 + a_csel);
                ldsm_x4(afr[mi][0], afr[mi][1], afr[mi][2], afr[mi][3], addr);
            }
            #pragma unroll
            for (int ni = 0; ni < 4; ni++) {
                uint32_t b0, b1, b2, b3;
                uint32_t addr = bBase + SMEM_SWZ128((b_row + ni * 16) * 128 + ks * 32 + b_csel);
                ldsm_x4(b0, b1, b2, b3, addr);
                #pragma unroll
                for (int mi = 0; mi < 2; mi++) {
                    mma16816(acc[mi][ni * 2 + 0], afr[mi], b0, b1);
                    mma16816(acc[mi][ni * 2 + 1], afr[mi], b2, b3);
                }
            }
        }
        // prefetch AFTER the MMA block: target stage was drained at chunk c-1
        if (c + 2 < NCHUNKS) load_chunk(c + 2, (c + 2) % NSTG);
    }

    // ---- epilogue ----
    const int er = lane >> 2;            // 0..7
    const int ec = (lane & 3) * 2;       // 0,2,4,6
    #pragma unroll
    for (int mi = 0; mi < 2; mi++) {
        #pragma unroll
        for (int j = 0; j < 8; j++) {
            float* base = C + (size_t)(m0 + wm * 32 + mi * 16 + er) * LDC
                            + n0 + wn * 64 + j * 8 + ec;
            *reinterpret_cast<float2*>(base) = make_float2(acc[mi][j][0], acc[mi][j][1]);
            *reinterpret_cast<float2*>(base + (size_t)8 * LDC) = make_float2(acc[mi][j][2], acc[mi][j][3]);
        }
    }
}

// ---------------- split-K reduction: out = sum of 8 partials (4 in S0, 4 in S1) ----------------
__global__ void __launch_bounds__(256) reduce8_kernel(float* __restrict__ out)
{
    const size_t i = (size_t)blockIdx.x * blockDim.x + threadIdx.x;   // float4 index
    const float4* p0 = reinterpret_cast<const float4*>(g_S0);
    const float4* p1 = reinterpret_cast<const float4*>(g_S1);
    constexpr size_t PART4 = (size_t)NT * DD / 4;
    float s0 = 0.f, s1 = 0.f, s2 = 0.f, s3 = 0.f;
    #pragma unroll
    for (int p = 0; p < 4; p++) {
        float4 a = p0[i + p * PART4];
        float4 b = p1[i + p * PART4];
        s0 += a.x + b.x; s1 += a.y + b.y; s2 += a.z + b.z; s3 += a.w + b.w;
    }
    reinterpret_cast<float4*>(out)[i] = make_float4(s0, s1, s2, s3);
}

// ---------------- fp32 -> bf16 hi/lo split ----------------
__global__ void __launch_bounds__(256) split_kernel(const float* __restrict__ x,
                                                    __nv_bfloat16* __restrict__ hi,
                                                    __nv_bfloat16* __restrict__ lo,
                                                    int n4)
{
    int i = blockIdx.x * blockDim.x + threadIdx.x;
    if (i >= n4) return;
    float4 v = reinterpret_cast<const float4*>(x)[i];
    __nv_bfloat16 h0 = __float2bfloat16(v.x), h1 = __float2bfloat16(v.y);
    __nv_bfloat16 h2 = __float2bfloat16(v.z), h3 = __float2bfloat16(v.w);
    __nv_bfloat16 l0 = __float2bfloat16(v.x - __bfloat162float(h0));
    __nv_bfloat16 l1 = __float2bfloat16(v.y - __bfloat162float(h1));
    __nv_bfloat16 l2 = __float2bfloat16(v.z - __bfloat162float(h2));
    __nv_bfloat16 l3 = __float2bfloat16(v.w - __bfloat162float(h3));
    reinterpret_cast<uint2*>(hi)[i] = make_uint2(packbf(h0, h1), packbf(h2, h3));
    reinterpret_cast<uint2*>(lo)[i] = make_uint2(packbf(l0, l1), packbf(l2, l3));
}

// ---------------- V transpose + split:  Vt[n][k] = V[k][n] ----------------
__global__ void __launch_bounds__(256) vtrans_kernel(const float* __restrict__ v)
{
    __shared__ float tile[32][33];
    const int n0 = blockIdx.x * 32;   // over DD
    const int k0 = blockIdx.y * 32;   // over NT
    const int tx = threadIdx.x, ty = threadIdx.y;  // (32, 8)
    #pragma unroll
    for (int j = 0; j < 32; j += 8)
        tile[ty + j][tx] = v[(size_t)(k0 + ty + j) * DD + n0 + tx];
    __syncthreads();
    #pragma unroll
    for (int j = 0; j < 32; j += 8) {
        const float val = tile[tx][ty + j];
        __nv_bfloat16 h = __float2bfloat16(val);
        __nv_bfloat16 l = __float2bfloat16(val - __bfloat162float(h));
        const size_t o = (size_t)(n0 + ty + j) * NT + k0 + tx;
        g_Vth[o] = h;
        g_Vtl[o] = l;
    }
}

// ---------------- softmax over S0 + normalize + bf16 hi/lo split of P ----------------
__global__ void __launch_bounds__(256) softmax_split()
{
    const int row = blockIdx.x;
    const int tid = threadIdx.x;
    const float4* p4 = reinterpret_cast<const float4*>(g_S0 + (size_t)row * NT);
    __shared__ float red[8];
    __shared__ float sh_inv;

    float4 v[4];
    #pragma unroll
    for (int it = 0; it < 4; it++) v[it] = p4[tid + it * 256];

    float m = -3.4e38f;
    #pragma unroll
    for (int it = 0; it < 4; it++)
        m = fmaxf(m, fmaxf(fmaxf(v[it].x, v[it].y), fmaxf(v[it].z, v[it].w)));
    #pragma unroll
    for (int o = 16; o > 0; o >>= 1) m = fmaxf(m, __shfl_xor_sync(0xffffffffu, m, o));
    if ((tid & 31) == 0) red[tid >> 5] = m;
    __syncthreads();
    float M = red[0];
    #pragma unroll
    for (int i = 1; i < 8; i++) M = fmaxf(M, red[i]);
    __syncthreads();

    float s = 0.0f;
    #pragma unroll
    for (int it = 0; it < 4; it++) {
        v[it].x = __expf(v[it].x - M);
        v[it].y = __expf(v[it].y - M);
        v[it].z = __expf(v[it].z - M);
        v[it].w = __expf(v[it].w - M);
        s += (v[it].x + v[it].y) + (v[it].z + v[it].w);
    }
    #pragma unroll
    for (int o = 16; o > 0; o >>= 1) s += __shfl_xor_sync(0xffffffffu, s, o);
    if ((tid & 31) == 0) red[tid >> 5] = s;
    __syncthreads();
    if (tid == 0) {
        float tot = 0.0f;
        #pragma unroll
        for (int i = 0; i < 8; i++) tot += red[i];
        sh_inv = 1.0f / tot;
    }
    __syncthreads();
    const float inv = sh_inv;

    uint2* ph2 = reinterpret_cast<uint2*>(g_Ph + (size_t)row * NT);
    uint2* pl2 = reinterpret_cast<uint2*>(g_Pl + (size_t)row * NT);
    #pragma unroll
    for (int it = 0; it < 4; it++) {
        float p0v = v[it].x * inv, p1v = v[it].y * inv, p2v = v[it].z * inv, p3v = v[it].w * inv;
        __nv_bfloat16 h0 = __float2bfloat16(p0v), h1 = __float2bfloat16(p1v);
        __nv_bfloat16 h2 = __float2bfloat16(p2v), h3 = __float2bfloat16(p3v);
        __nv_bfloat16 l0 = __float2bfloat16(p0v - __bfloat162float(h0));
        __nv_bfloat16 l1 = __float2bfloat16(p1v - __bfloat162float(h1));
        __nv_bfloat16 l2 = __float2bfloat16(p2v - __bfloat162float(h2));
        __nv_bfloat16 l3 = __float2bfloat16(p3v - __bfloat162float(h3));
        const int idx = tid + it * 256;
        ph2[idx] = make_uint2(packbf(h0, h1), packbf(h2, h3));
        pl2[idx] = make_uint2(packbf(l0, l1), packbf(l2, l3));
    }
}

// ---------------- launch ----------------
extern "C" void kernel_launch(void* const* d_in, const int* in_sizes, int n_in,
                              void* d_out, int out_size)
{
    const float* q = (const float*)d_in[0];
    const float* k = (const float*)d_in[1];
    const float* v = (const float*)d_in[2];
    float* out = (float*)d_out;

    void *qh, *ql, *kh, *kl, *s0, *s1, *ph, *pl, *vth, *vtl;
    cudaGetSymbolAddress(&qh, g_Qh);  cudaGetSymbolAddress(&ql, g_Ql);
    cudaGetSymbolAddress(&kh, g_Kh);  cudaGetSymbolAddress(&kl, g_Kl);
    cudaGetSymbolAddress(&s0, g_S0);  cudaGetSymbolAddress(&s1, g_S1);
    cudaGetSymbolAddress(&ph, g_Ph);  cudaGetSymbolAddress(&pl, g_Pl);
    cudaGetSymbolAddress(&vth, g_Vth); cudaGetSymbolAddress(&vtl, g_Vtl);

    // qk: unsplit: A=Q, B=K, KEXT=1024, single z -> full S in g_S0
    auto qk = mma_gemm<DD, DD, NT, 0LL, 1024, 1>;
    // pv: split-K x8: KEXT=512, 4 parts in S0 + 4 in S1
    auto pv = mma_gemm<NT, NT, DD, (long long)NT * DD, 512, 4>;
    cudaFuncSetAttribute(qk, cudaFuncAttributeMaxDynamicSharedMemorySize, SMEM_TOTAL);
    cudaFuncSetAttribute(pv, cudaFuncAttributeMaxDynamicSharedMemorySize, SMEM_TOTAL);

    const int n4 = NT * DD / 4;
    split_kernel<<<(n4 + 255) / 256, 256>>>(q, (__nv_bfloat16*)qh, (__nv_bfloat16*)ql, n4);
    split_kernel<<<(n4 + 255) / 256, 256>>>(k, (__nv_bfloat16*)kh, (__nv_bfloat16*)kl, n4);
    vtrans_kernel<<<dim3(DD / 32, NT / 32), dim3(32, 8)>>>(v);

    // S = Q K^T   (grid 32 x 32 = 1024 CTAs)
    qk<<<dim3(NT / GBN, NT / GBM, 1), 256, SMEM_TOTAL>>>(
        (const __nv_bfloat16*)qh, (const __nv_bfloat16*)ql,
        (const __nv_bfloat16*)kh, (const __nv_bfloat16*)kl,
        (float*)s0, (float*)s1);

    softmax_split<<<NT, 256>>>();

    // O = P V via split-K x8  (grid 8 x 32 x 8 = 2048 CTAs)
    pv<<<dim3(DD / GBN, NT / GBM, 8), 256, SMEM_TOTAL>>>(
        (const __nv_bfloat16*)ph, (const __nv_bfloat16*)pl,
        (const __nv_bfloat16*)vth, (const __nv_bfloat16*)vtl,
        (float*)s0, (float*)s1);

    reduce8_kernel<<<(NT * DD / 4) / 256, 256>>>(out);
}

// round 17
// speedup vs baseline: 1.0426x; 1.0065x over previous
#include <cuda_runtime.h>
#include <cuda_bf16.h>
#include <cstdint>
#include <cstddef>

#define NT 4096   // sequence length
#define DD 1024   // head dim

// ---------------- device scratch (no allocs allowed) ----------------
// g_S0/g_S1: pv split-K fp32 partial buffers (4 parts in each).
__device__ float         g_S0[(size_t)NT * NT];    // 64 MB
__device__ float         g_S1[(size_t)NT * NT];    // 64 MB
__device__ __nv_bfloat16 g_Qh[(size_t)NT * DD];
__device__ __nv_bfloat16 g_Ql[(size_t)NT * DD];
__device__ __nv_bfloat16 g_Kh[(size_t)NT * DD];
__device__ __nv_bfloat16 g_Kl[(size_t)NT * DD];
__device__ __nv_bfloat16 g_Eh[(size_t)NT * NT];    // exp(S-130) hi, 32 MB
__device__ __nv_bfloat16 g_El[(size_t)NT * NT];    // exp(S-130) lo, 32 MB
__device__ __nv_bfloat16 g_Vth[(size_t)DD * NT];   // V^T hi  [1024][4096]
__device__ __nv_bfloat16 g_Vtl[(size_t)DD * NT];   // V^T lo
__device__ float         g_tsum[(size_t)32 * NT];  // per (ntile, row) exp-sums
__device__ float         g_inv[NT];                // 1 / row sum

#define EXP_SHIFT 130.0f

// ---------------- helpers ----------------
__device__ __forceinline__ uint32_t smem_u32(const void* p) {
    uint32_t a;
    asm("{ .reg .u64 t; cvta.to.shared.u64 t, %1; cvt.u32.u64 %0, t; }" : "=r"(a) : "l"(p));
    return a;
}
#define SMEM_SWZ128(b) ((b) ^ (((b) >> 3) & 0x70))

__device__ __forceinline__ void cp_async16(uint32_t dst, const void* src) {
    asm volatile("cp.async.cg.shared.global [%0], [%1], 16;" :: "r"(dst), "l"(src));
}
__device__ __forceinline__ void cp_commit() { asm volatile("cp.async.commit_group;" ::: "memory"); }
template<int N> __device__ __forceinline__ void cp_wait() {
    asm volatile("cp.async.wait_group %0;" :: "n"(N) : "memory");
}

__device__ __forceinline__ void ldsm_x4(uint32_t& r0, uint32_t& r1, uint32_t& r2, uint32_t& r3,
                                        uint32_t addr) {
    asm volatile("ldmatrix.sync.aligned.m8n8.x4.shared.b16 {%0,%1,%2,%3}, [%4];"
                 : "=r"(r0), "=r"(r1), "=r"(r2), "=r"(r3) : "r"(addr));
}

__device__ __forceinline__ void mma16816(float* d, const uint32_t* a, uint32_t b0, uint32_t b1) {
    asm volatile(
        "mma.sync.aligned.m16n8k16.row.col.f32.bf16.bf16.f32 "
        "{%0,%1,%2,%3}, {%4,%5,%6,%7}, {%8,%9}, {%0,%1,%2,%3};"
        : "+f"(d[0]), "+f"(d[1]), "+f"(d[2]), "+f"(d[3])
        : "r"(a[0]), "r"(a[1]), "r"(a[2]), "r"(a[3]), "r"(b0), "r"(b1));
}

__device__ __forceinline__ uint32_t packbf(__nv_bfloat16 a, __nv_bfloat16 b) {
    __nv_bfloat162 t; t.x = a; t.y = b;
    return *reinterpret_cast<uint32_t*>(&t);
}

// ---------------- GEMM config (R16 engine: 3-stage, 1 sync, post-MMA prefetch) ----------------
constexpr int GBM = 128, GBN = 128, GBK = 64;   // K chunk = 64 bf16 = 128B row
constexpr int NSTG = 3;
constexpr int TILE_BYTES = GBM * 128;            // 16 KB (A or B tile per stage)
constexpr int STAGE_BYTES = 2 * TILE_BYTES;      // 32 KB per stage (A+B)
constexpr int SMEM_NEED = NSTG * STAGE_BYTES;    // 96 KB -> 2 CTAs/SM
constexpr int SMEM_TOTAL = SMEM_NEED + 1024;

// D[m][n] = Ah*Bh + Al*Bh + Ah*Bl over K = KEXT (split-K part blockIdx.z).
// DO_EXP=0: write fp32 D to C (split-K partial buffers).
// DO_EXP=1: write bf16 hi/lo of exp(D - EXP_SHIFT) to Eh/El + per-tile row sums.
template<int LDA, int LDB, int LDC, long long PART_STR, int KEXT, int PPB, int DO_EXP>
__global__ void __launch_bounds__(256, 2)
mma_gemm(const __nv_bfloat16* __restrict__ Ah, const __nv_bfloat16* __restrict__ Al,
         const __nv_bfloat16* __restrict__ Bh, const __nv_bfloat16* __restrict__ Bl,
         float* __restrict__ C0, float* __restrict__ C1)
{
    extern __shared__ char smem_raw[];
    const uint32_t sb = (smem_u32(smem_raw) + 1023u) & ~1023u;
    const int tid = threadIdx.x;
    const int wid = tid >> 5;
    const int lane = tid & 31;
    const int m0 = blockIdx.y * GBM;
    const int n0 = blockIdx.x * GBN;

    const int z = blockIdx.z;
    const size_t kbase = (size_t)z * KEXT;
    Ah += kbase; Al += kbase; Bh += kbase; Bl += kbase;
    float* __restrict__ C = (z < PPB) ? C0 : C1;
    C += (size_t)(z % PPB) * (size_t)PART_STR;

    const int wm = wid & 3;        // 4 warp-rows of 32
    const int wn = wid >> 2;       // 2 warp-cols of 64

    constexpr int CPP = KEXT / GBK;       // chunks per phase
    constexpr int NCHUNKS = 3 * CPP;      // hh, lh, hl

    const __nv_bfloat16* Asrc[3] = {Ah, Al, Ah};
    const __nv_bfloat16* Bsrc[3] = {Bh, Bh, Bl};

    auto load_chunk = [&](int c, int s) {
        const int ph = c / CPP;
        const int koff = (c % CPP) * GBK;
        const char* srcA = (const char*)(Asrc[ph] + (size_t)m0 * LDA + koff);
        const char* srcB = (const char*)(Bsrc[ph] + (size_t)n0 * LDB + koff);
        const uint32_t baseA = sb + s * STAGE_BYTES;
        const uint32_t baseB = baseA + TILE_BYTES;
        #pragma unroll
        for (int t = 0; t < 4; t++) {
            int idx = tid + t * 256;
            int r = idx >> 3;
            int cB = (idx & 7) * 16;
            cp_async16(baseA + SMEM_SWZ128(r * 128 + cB), srcA + (size_t)r * (LDA * 2) + cB);
        }
        #pragma unroll
        for (int t = 0; t < 4; t++) {
            int idx = tid + t * 256;
            int r = idx >> 3;
            int cB = (idx & 7) * 16;
            cp_async16(baseB + SMEM_SWZ128(r * 128 + cB), srcB + (size_t)r * (LDB * 2) + cB);
        }
        cp_commit();
    };

    float acc[2][8][4];
    #pragma unroll
    for (int i = 0; i < 2; i++)
        #pragma unroll
        for (int j = 0; j < 8; j++)
            #pragma unroll
            for (int q = 0; q < 4; q++) acc[i][j][q] = 0.0f;

    load_chunk(0, 0);
    load_chunk(1, 1);

    const int a_row  = wm * 32 + (lane & 15);
    const int a_csel = (lane >> 4) << 4;
    const int b_row  = wn * 64 + (lane & 7) + ((lane >> 4) << 3);
    const int b_csel = ((lane >> 3) & 1) << 4;

    for (int c = 0; c < NCHUNKS; c++) {
        const int s = c % NSTG;
        cp_wait<1>();
        __syncthreads();
        const uint32_t aBase = sb + s * STAGE_BYTES;
        const uint32_t bBase = aBase + TILE_BYTES;
        #pragma unroll
        for (int ks = 0; ks < 4; ks++) {
            uint32_t afr[2][4];
            #pragma unroll
            for (int mi = 0; mi < 2; mi++) {
                uint32_t addr = aBase + SMEM_SWZ128((a_row + mi * 16) * 128 + ks * 32 + a_csel);
                ldsm_x4(afr[mi][0], afr[mi][1], afr[mi][2], afr[mi][3], addr);
            }
            #pragma unroll
            for (int ni = 0; ni < 4; ni++) {
                uint32_t b0, b1, b2, b3;
                uint32_t addr = bBase + SMEM_SWZ128((b_row + ni * 16) * 128 + ks * 32 + b_csel);
                ldsm_x4(b0, b1, b2, b3, addr);
                #pragma unroll
                for (int mi = 0; mi < 2; mi++) {
                    mma16816(acc[mi][ni * 2 + 0], afr[mi], b0, b1);
                    mma16816(acc[mi][ni * 2 + 1], afr[mi], b2, b3);
                }
            }
        }
        if (c + 2 < NCHUNKS) load_chunk(c + 2, (c + 2) % NSTG);
    }

    const int er = lane >> 2;            // 0..7
    const int ec = (lane & 3) * 2;       // 0,2,4,6

    if constexpr (DO_EXP == 0) {
        // plain fp32 partial store
        #pragma unroll
        for (int mi = 0; mi < 2; mi++) {
            #pragma unroll
            for (int j = 0; j < 8; j++) {
                float* base = C + (size_t)(m0 + wm * 32 + mi * 16 + er) * LDC
                                + n0 + wn * 64 + j * 8 + ec;
                *reinterpret_cast<float2*>(base) = make_float2(acc[mi][j][0], acc[mi][j][1]);
                *reinterpret_cast<float2*>(base + (size_t)8 * LDC) = make_float2(acc[mi][j][2], acc[mi][j][3]);
            }
        }
    } else {
        // exp(s - SHIFT) -> bf16 hi/lo, plus per-tile row-sum reduction
        __syncthreads();                      // pipeline smem free for reuse
        float* sred = reinterpret_cast<float*>(smem_raw);   // 2 x 128 floats
        float rsum[2][2] = {{0.f, 0.f}, {0.f, 0.f}};        // [mi][row er / er+8]
        #pragma unroll
        for (int mi = 0; mi < 2; mi++) {
            const int row0 = m0 + wm * 32 + mi * 16 + er;
            #pragma unroll
            for (int j = 0; j < 8; j++) {
                const int col = n0 + wn * 64 + j * 8 + ec;
                float e0 = __expf(acc[mi][j][0] - EXP_SHIFT);
                float e1 = __expf(acc[mi][j][1] - EXP_SHIFT);
                float e2 = __expf(acc[mi][j][2] - EXP_SHIFT);
                float e3 = __expf(acc[mi][j][3] - EXP_SHIFT);
                __nv_bfloat16 h0 = __float2bfloat16(e0), h1 = __float2bfloat16(e1);
                __nv_bfloat16 h2 = __float2bfloat16(e2), h3 = __float2bfloat16(e3);
                __nv_bfloat16 l0 = __float2bfloat16(e0 - __bfloat162float(h0));
                __nv_bfloat16 l1 = __float2bfloat16(e1 - __bfloat162float(h1));
                __nv_bfloat16 l2 = __float2bfloat16(e2 - __bfloat162float(h2));
                __nv_bfloat16 l3 = __float2bfloat16(e3 - __bfloat162float(h3));
                *reinterpret_cast<uint32_t*>(g_Eh + (size_t)row0 * NT + col) = packbf(h0, h1);
                *reinterpret_cast<uint32_t*>(g_El + (size_t)row0 * NT + col) = packbf(l0, l1);
                *reinterpret_cast<uint32_t*>(g_Eh + (size_t)(row0 + 8) * NT + col) = packbf(h2, h3);
                *reinterpret_cast<uint32_t*>(g_El + (size_t)(row0 + 8) * NT + col) = packbf(l2, l3);
                rsum[mi][0] += e0 + e1;
                rsum[mi][1] += e2 + e3;
            }
        }
        // reduce across the 4 lanes of each row-quad
        #pragma unroll
        for (int off = 1; off <= 2; off <<= 1) {
            #pragma unroll
            for (int mi = 0; mi < 2; mi++) {
                rsum[mi][0] += __shfl_xor_sync(0xffffffffu, rsum[mi][0], off);
                rsum[mi][1] += __shfl_xor_sync(0xffffffffu, rsum[mi][1], off);
            }
        }
        if ((lane & 3) == 0) {
            #pragma unroll
            for (int mi = 0; mi < 2; mi++) {
                sred[wn * 128 + wm * 32 + mi * 16 + er]     = rsum[mi][0];
                sred[wn * 128 + wm * 32 + mi * 16 + er + 8] = rsum[mi][1];
            }
        }
        __syncthreads();
        if (tid < 128)
            g_tsum[(size_t)blockIdx.x * NT + m0 + tid] = sred[tid] + sred[128 + tid];
    }
}

// ---------------- row inverse: inv[m] = 1 / sum over 32 tile-sums ----------------
__global__ void __launch_bounds__(256) rowinv_kernel()
{
    const int m = blockIdx.x * 256 + threadIdx.x;
    float s = 0.0f;
    #pragma unroll
    for (int nt = 0; nt < 32; nt++) s += g_tsum[(size_t)nt * NT + m];
    g_inv[m] = 1.0f / s;
}

// ---------------- split-K reduction with normalization ----------------
__global__ void __launch_bounds__(256) reduce8_kernel(float* __restrict__ out)
{
    const size_t i = (size_t)blockIdx.x * blockDim.x + threadIdx.x;   // float4 index
    const float4* p0 = reinterpret_cast<const float4*>(g_S0);
    const float4* p1 = reinterpret_cast<const float4*>(g_S1);
    constexpr size_t PART4 = (size_t)NT * DD / 4;
    const int m = (int)(i >> 8);                  // row = i / (DD/4)
    const float inv = g_inv[m];
    float s0 = 0.f, s1 = 0.f, s2 = 0.f, s3 = 0.f;
    #pragma unroll
    for (int p = 0; p < 4; p++) {
        float4 a = p0[i + p * PART4];
        float4 b = p1[i + p * PART4];
        s0 += a.x + b.x; s1 += a.y + b.y; s2 += a.z + b.z; s3 += a.w + b.w;
    }
    reinterpret_cast<float4*>(out)[i] = make_float4(s0 * inv, s1 * inv, s2 * inv, s3 * inv);
}

// ---------------- fp32 -> bf16 hi/lo split (q and k in one launch via blockIdx.y) ----------------
__global__ void __launch_bounds__(256) split_qk_kernel(const float* __restrict__ q,
                                                       const float* __restrict__ k)
{
    const int i = blockIdx.x * 256 + threadIdx.x;   // float4 index, NT*DD/4 total
    const float* x = blockIdx.y ? k : q;
    __nv_bfloat16* hi = blockIdx.y ? g_Kh : g_Qh;
    __nv_bfloat16* lo = blockIdx.y ? g_Kl : g_Ql;
    float4 v = reinterpret_cast<const float4*>(x)[i];
    __nv_bfloat16 h0 = __float2bfloat16(v.x), h1 = __float2bfloat16(v.y);
    __nv_bfloat16 h2 = __float2bfloat16(v.z), h3 = __float2bfloat16(v.w);
    __nv_bfloat16 l0 = __float2bfloat16(v.x - __bfloat162float(h0));
    __nv_bfloat16 l1 = __float2bfloat16(v.y - __bfloat162float(h1));
    __nv_bfloat16 l2 = __float2bfloat16(v.z - __bfloat162float(h2));
    __nv_bfloat16 l3 = __float2bfloat16(v.w - __bfloat162float(h3));
    reinterpret_cast<uint2*>(hi)[i] = make_uint2(packbf(h0, h1), packbf(h2, h3));
    reinterpret_cast<uint2*>(lo)[i] = make_uint2(packbf(l0, l1), packbf(l2, l3));
}

// ---------------- V transpose + split:  Vt[n][k] = V[k][n] ----------------
__global__ void __launch_bounds__(256) vtrans_kernel(const float* __restrict__ v)
{
    __shared__ float tile[32][33];
    const int n0 = blockIdx.x * 32;   // over DD
    const int k0 = blockIdx.y * 32;   // over NT
    const int tx = threadIdx.x, ty = threadIdx.y;  // (32, 8)
    #pragma unroll
    for (int j = 0; j < 32; j += 8)
        tile[ty + j][tx] = v[(size_t)(k0 + ty + j) * DD + n0 + tx];
    __syncthreads();
    #pragma unroll
    for (int j = 0; j < 32; j += 8) {
        const float val = tile[tx][ty + j];
        __nv_bfloat16 h = __float2bfloat16(val);
        __nv_bfloat16 l = __float2bfloat16(val - __bfloat162float(h));
        const size_t o = (size_t)(n0 + ty + j) * NT + k0 + tx;
        g_Vth[o] = h;
        g_Vtl[o] = l;
    }
}

// ---------------- launch ----------------
extern "C" void kernel_launch(void* const* d_in, const int* in_sizes, int n_in,
                              void* d_out, int out_size)
{
    const float* q = (const float*)d_in[0];
    const float* k = (const float*)d_in[1];
    const float* v = (const float*)d_in[2];
    float* out = (float*)d_out;

    void *qh, *ql, *kh, *kl, *s0, *s1, *eh, *el, *vth, *vtl;
    cudaGetSymbolAddress(&qh, g_Qh);  cudaGetSymbolAddress(&ql, g_Ql);
    cudaGetSymbolAddress(&kh, g_Kh);  cudaGetSymbolAddress(&kl, g_Kl);
    cudaGetSymbolAddress(&s0, g_S0);  cudaGetSymbolAddress(&s1, g_S1);
    cudaGetSymbolAddress(&eh, g_Eh);  cudaGetSymbolAddress(&el, g_El);
    cudaGetSymbolAddress(&vth, g_Vth); cudaGetSymbolAddress(&vtl, g_Vtl);

    // qk: unsplit, exp-epilogue: writes g_Eh/g_El + g_tsum (C unused)
    auto qk = mma_gemm<DD, DD, NT, 0LL, 1024, 1, 1>;
    // pv: split-K x8, plain epilogue: KEXT=512, 4 parts in S0 + 4 in S1
    auto pv = mma_gemm<NT, NT, DD, (long long)NT * DD, 512, 4, 0>;
    cudaFuncSetAttribute(qk, cudaFuncAttributeMaxDynamicSharedMemorySize, SMEM_TOTAL);
    cudaFuncSetAttribute(pv, cudaFuncAttributeMaxDynamicSharedMemorySize, SMEM_TOTAL);

    const int n4 = NT * DD / 4;
    split_qk_kernel<<<dim3(n4 / 256, 2), 256>>>(q, k);
    vtrans_kernel<<<dim3(DD / 32, NT / 32), dim3(32, 8)>>>(v);

    // E = exp(Q K^T - 130)  (grid 32 x 32 = 1024 CTAs)
    qk<<<dim3(NT / GBN, NT / GBM, 1), 256, SMEM_TOTAL>>>(
        (const __nv_bfloat16*)qh, (const __nv_bfloat16*)ql,
        (const __nv_bfloat16*)kh, (const __nv_bfloat16*)kl,
        (float*)s0, (float*)s1);

    rowinv_kernel<<<NT / 256, 256>>>();

    // O' = E V via split-K x8  (grid 8 x 32 x 8 = 2048 CTAs)
    pv<<<dim3(DD / GBN, NT / GBM, 8), 256, SMEM_TOTAL>>>(
        (const __nv_bfloat16*)eh, (const __nv_bfloat16*)el,
        (const __nv_bfloat16*)vth, (const __nv_bfloat16*)vtl,
        (float*)s0, (float*)s1);

    // out = O' * inv[m]
    reduce8_kernel<<<(NT * DD / 4) / 256, 256>>>(out);
}